// round 2
// baseline (speedup 1.0000x reference)
#include <cuda_runtime.h>
#include <cuda_fp16.h>
#include <cstdint>
#include <cstddef>

#define B_  128
#define S_  512
#define I_  128
#define H_  128
#define M_  8
#define KD_ 16
#define R_  16
#define O_  128
#define MH_ 1024

#define OUT_OUTPUTS 0ull
#define OUT_HID     8388608ull
#define OUT_AIN     75497472ull
#define OUT_ACM     142606336ull
#define OUT_ATTN    209715200ull

__device__ float g_P[(size_t)S_ * B_ * MH_];
__device__ float g_Wcomb[M_ * I_ * H_];

// ---------------------------------------------------------------------------
// Kernel 0: Wcomb[m,i,o] = sum_h W_in[m,i,h] * Wp[m,o,h]
// ---------------------------------------------------------------------------
__global__ void __launch_bounds__(256) prep_wcomb(const float* __restrict__ W_in,
                                                  const float* __restrict__ Wp) {
    extern __shared__ float s0[];
    float* Wins = s0;                 // [i][h]
    float* Wps  = s0 + 16384;         // [o][h] stride 129
    int m = blockIdx.x, tid = threadIdx.x;
    const float* wi = W_in + m * 16384;
    const float* wp = Wp   + m * 16384;
    for (int i = tid; i < 16384; i += 256) {
        Wins[i] = wi[i];
        Wps[(i >> 7) * 129 + (i & 127)] = wp[i];
    }
    __syncthreads();
    for (int idx = tid; idx < 16384; idx += 256) {
        int j = idx >> 7, o = idx & 127;
        const float* a = Wins + j * 128;
        const float* b = Wps + o * 129;
        float acc = 0.f;
#pragma unroll 16
        for (int i = 0; i < 128; ++i) acc += a[i] * b[i];
        g_Wcomb[m * 16384 + idx] = acc;
    }
}

// ---------------------------------------------------------------------------
// Kernel A: per (t, colblock) 128x128 GEMM, K=128.
//  cb<8 : A_in[:,m,:] = x_t . W_in[m]        -> d_out AIN
//  cb>=8: P[:,m,:]    = x_t . Wcomb[m] + b   -> g_P
// ---------------------------------------------------------------------------
__global__ void __launch_bounds__(512) gemm_in_kernel(const float* __restrict__ x,
                                                      const float* __restrict__ W_in,
                                                      const float* __restrict__ bp,
                                                      const float* __restrict__ cbias,
                                                      float* __restrict__ out) {
    extern __shared__ float sA[];
    float* xs = sA;           // [k][b]
    float* ws = sA + 16384;   // [k][c]
    int t = blockIdx.y, cb = blockIdx.x, tid = threadIdx.x;
    int m = cb & 7;
    bool isP = (cb >= 8);
    const float* Wsrc = (isP ? g_Wcomb : W_in) + m * 16384;

    {
        int b = tid >> 2, q4 = (tid & 3) * 32;
        const float4* xr = (const float4*)(x + ((size_t)b * S_ + t) * I_ + q4);
#pragma unroll
        for (int q = 0; q < 8; ++q) {
            float4 v = xr[q];
            int k = q4 + q * 4;
            xs[(k + 0) * 128 + b] = v.x;
            xs[(k + 1) * 128 + b] = v.y;
            xs[(k + 2) * 128 + b] = v.z;
            xs[(k + 3) * 128 + b] = v.w;
        }
        const float4* wr = (const float4*)(Wsrc + b * 128 + q4);
        float4* wd = (float4*)(ws + b * 128 + q4);
#pragma unroll
        for (int q = 0; q < 8; ++q) wd[q] = wr[q];
    }
    __syncthreads();

    int tr = tid >> 5, tc = tid & 31;
    float acc[8][4];
#pragma unroll
    for (int i = 0; i < 8; ++i)
#pragma unroll
        for (int j = 0; j < 4; ++j) acc[i][j] = 0.f;

#pragma unroll 4
    for (int k = 0; k < 128; ++k) {
        float4 a0 = *(const float4*)(xs + k * 128 + tr * 8);
        float4 a1 = *(const float4*)(xs + k * 128 + tr * 8 + 4);
        float4 bb = *(const float4*)(ws + k * 128 + tc * 4);
        float av[8] = {a0.x, a0.y, a0.z, a0.w, a1.x, a1.y, a1.z, a1.w};
        float bv[4] = {bb.x, bb.y, bb.z, bb.w};
#pragma unroll
        for (int i = 0; i < 8; ++i)
#pragma unroll
            for (int j = 0; j < 4; ++j) acc[i][j] += av[i] * bv[j];
    }

    if (!isP) {
#pragma unroll
        for (int i = 0; i < 8; ++i) {
            int b = tr * 8 + i;
            float* dst = out + OUT_AIN + ((size_t)t * B_ + b) * MH_ + m * H_ + tc * 4;
            *(float4*)dst = make_float4(acc[i][0], acc[i][1], acc[i][2], acc[i][3]);
        }
    } else {
        float bias[4];
#pragma unroll
        for (int j = 0; j < 4; ++j) {
            int c = m * H_ + tc * 4 + j;
            bias[j] = bp[c] + cbias[c];
        }
#pragma unroll
        for (int i = 0; i < 8; ++i) {
            int b = tr * 8 + i;
            float* dst = g_P + ((size_t)t * B_ + b) * MH_ + m * H_ + tc * 4;
            *(float4*)dst = make_float4(acc[i][0] + bias[0], acc[i][1] + bias[1],
                                        acc[i][2] + bias[2], acc[i][3] + bias[3]);
        }
    }
}

// ---------------------------------------------------------------------------
// Kernel B: sequential recurrence, one CTA per batch element.
// ---------------------------------------------------------------------------
__global__ void __launch_bounds__(512) rim_seq_kernel(const float* __restrict__ U,
                                                      const float* __restrict__ V,
                                                      const float* __restrict__ WQ,
                                                      const float* __restrict__ WK,
                                                      const float* __restrict__ WV,
                                                      float* __restrict__ out) {
    extern __shared__ float smf[];
    float* Us   = smf;                // [m][h][r]
    float* Vs   = Us + 16384;         // [m][r][h]
    float* wvd  = Vs + 16384;         // [m][h]
    float* Ssm  = wvd + 1024;         // state
    float* his  = Ssm + 1024;         // H_in
    float* vcs  = his + 1024;         // H_in * wvd
    float* tmp  = vcs + 1024;         // [m][r]
    float* Kc   = tmp + 128;          // [m][k]
    float* Qc   = Kc + 128;           // [m][k]
    float* attn = Qc + 128;           // [m][n]
    __half* WKh = (__half*)(attn + 64);
    __half* WQh = WKh + 16384;

    int tid = threadIdx.x, b = blockIdx.x;
    for (int i = tid; i < 16384; i += 512) {
        Us[i] = U[i];
        Vs[i] = V[i];
        WKh[i] = __float2half(WK[i]);
        WQh[i] = __float2half(WQ[i]);
    }
    for (int i = tid; i < 1024; i += 512) {
        int m = i >> 7, h = i & 127;
        wvd[i] = WV[m * 16384 + h * 128 + h];
        Ssm[i] = 0.f;
    }
    __syncthreads();

    int w = tid >> 5, lane = tid & 31;
    int ma = w >> 1, rbase = (w & 1) * 8, rl = lane >> 2, hq = lane & 3, rr = rbase + rl;
    int mc = w >> 1, isQ = w & 1, kk = lane >> 1, hh = lane & 1;
    const __half* Wch = (isQ ? WQh : WKh) + mc * 2048;
    float* Xc = isQ ? Qc : Kc;

    float p0 = g_P[(size_t)b * MH_ + tid];
    float p1 = g_P[(size_t)b * MH_ + tid + 512];

    for (int t = 0; t < S_; ++t) {
        // a: tmp[m,r] = sum_h S[m,h]*U[m,h,r]
        {
            float acc = 0.f;
            const float* Su = Ssm + ma * 128;
            const float* Uu = Us + ma * 2048 + rr;
#pragma unroll 8
            for (int j = 0; j < 32; ++j) {
                int h = hq + 4 * j;
                acc += Su[h] * Uu[h * 16];
            }
            acc += __shfl_xor_sync(0xffffffffu, acc, 1);
            acc += __shfl_xor_sync(0xffffffffu, acc, 2);
            if (hq == 0) tmp[ma * 16 + rr] = acc;
        }
        __syncthreads();

        // b: H_in = tanh(P + tmp.V); Vc diag product
        {
            float z0 = p0, z1 = p1;
            int i0 = tid, i1 = tid + 512;
            int m0 = i0 >> 7, h0 = i0 & 127;
            int m1 = i1 >> 7, h1 = i1 & 127;
            const float* t0 = tmp + m0 * 16;
            const float* t1 = tmp + m1 * 16;
            const float* V0 = Vs + m0 * 2048 + h0;
            const float* V1 = Vs + m1 * 2048 + h1;
#pragma unroll
            for (int r = 0; r < 16; ++r) {
                z0 += t0[r] * V0[r * 128];
                z1 += t1[r] * V1[r * 128];
            }
            float hin0 = tanhf(z0), hin1 = tanhf(z1);
            his[i0] = hin0; his[i1] = hin1;
            vcs[i0] = hin0 * wvd[i0];
            vcs[i1] = hin1 * wvd[i1];
        }
        if (t + 1 < S_) {
            size_t base = ((size_t)(t + 1) * B_ + b) * MH_;
            p0 = g_P[base + tid];
            p1 = g_P[base + tid + 512];
        }
        __syncthreads();

        // c: Kc/Qc[m,k] = sum_h H_in[m,h]*W[m,h,k]
        {
            float acc = 0.f;
            const float* hm = his + mc * 128;
#pragma unroll 8
            for (int j = 0; j < 64; ++j) {
                int h = hh + 2 * j;
                acc += hm[h] * __half2float(Wch[h * 16 + kk]);
            }
            acc += __shfl_xor_sync(0xffffffffu, acc, 1);
            if (hh == 0) Xc[mc * 16 + kk] = acc;
        }
        __syncthreads();

        // d: attn[m,n] = softmax_n(Qc[m].Kc[n] * 0.25)
        if (w < 8) {
            int n = lane & 7;
            const float* q = Qc + w * 16;
            const float* k2 = Kc + n * 16;
            float lg = 0.f;
#pragma unroll
            for (int k = 0; k < 16; ++k) lg += q[k] * k2[k];
            lg *= 0.25f;
            float mx = lg;
            mx = fmaxf(mx, __shfl_xor_sync(0xffffffffu, mx, 1));
            mx = fmaxf(mx, __shfl_xor_sync(0xffffffffu, mx, 2));
            mx = fmaxf(mx, __shfl_xor_sync(0xffffffffu, mx, 4));
            float e = expf(lg - mx);
            float sm2 = e;
            sm2 += __shfl_xor_sync(0xffffffffu, sm2, 1);
            sm2 += __shfl_xor_sync(0xffffffffu, sm2, 2);
            sm2 += __shfl_xor_sync(0xffffffffu, sm2, 4);
            float a3 = e / sm2;
            if (lane < 8) {
                attn[w * 8 + n] = a3;
                out[OUT_ATTN + ((size_t)t * B_ + b) * 64 + w * 8 + n] = a3;
            }
        }
        __syncthreads();

        // e: A_comm[n,h] = sum_m attn[m,n]*vcs[m,h]; H_new = H_in + A_comm
        {
            size_t gbase = ((size_t)t * B_ + b) * MH_;
#pragma unroll
            for (int rep = 0; rep < 2; ++rep) {
                int idx = tid + rep * 512;
                int n = idx >> 7, h = idx & 127;
                float ac = 0.f;
#pragma unroll
                for (int m = 0; m < 8; ++m) ac += attn[m * 8 + n] * vcs[m * 128 + h];
                float hnew = his[idx] + ac;
                out[OUT_ACM + gbase + idx] = ac;
                out[OUT_HID + gbase + idx] = hnew;
                Ssm[idx] = hnew;
            }
        }
        __syncthreads();
    }
}

// ---------------------------------------------------------------------------
// Kernel C: outputs[b,t,:] = hiddens[t,b,:] . Wo^T + bo    (K=1024)
// ---------------------------------------------------------------------------
__global__ void __launch_bounds__(512) gemm_out_kernel(const float* __restrict__ Wo,
                                                       const float* __restrict__ bo,
                                                       float* __restrict__ out) {
    extern __shared__ float sC[];
    float* xs = sC;           // [k][b]
    float* ws = sC + 16384;   // [k][o]
    int t = blockIdx.x, tid = threadIdx.x;
    const float* hid = out + OUT_HID + (size_t)t * B_ * MH_;

    int tr = tid >> 5, tc = tid & 31;
    float acc[8][4];
#pragma unroll
    for (int i = 0; i < 8; ++i)
#pragma unroll
        for (int j = 0; j < 4; ++j) acc[i][j] = 0.f;

    int bld = tid >> 2, q4 = (tid & 3) * 32;
    for (int kc = 0; kc < 8; ++kc) {
        int k0 = kc * 128;
        const float4* xr = (const float4*)(hid + (size_t)bld * MH_ + k0 + q4);
        const float4* wr = (const float4*)(Wo + (size_t)bld * MH_ + k0 + q4);
#pragma unroll
        for (int q = 0; q < 8; ++q) {
            float4 v = xr[q];
            float4 wv = wr[q];
            int k = q4 + q * 4;
            xs[(k + 0) * 128 + bld] = v.x;
            xs[(k + 1) * 128 + bld] = v.y;
            xs[(k + 2) * 128 + bld] = v.z;
            xs[(k + 3) * 128 + bld] = v.w;
            ws[(k + 0) * 128 + bld] = wv.x;
            ws[(k + 1) * 128 + bld] = wv.y;
            ws[(k + 2) * 128 + bld] = wv.z;
            ws[(k + 3) * 128 + bld] = wv.w;
        }
        __syncthreads();
#pragma unroll 4
        for (int k = 0; k < 128; ++k) {
            float4 a0 = *(const float4*)(xs + k * 128 + tr * 8);
            float4 a1 = *(const float4*)(xs + k * 128 + tr * 8 + 4);
            float4 bb = *(const float4*)(ws + k * 128 + tc * 4);
            float av[8] = {a0.x, a0.y, a0.z, a0.w, a1.x, a1.y, a1.z, a1.w};
            float bv[4] = {bb.x, bb.y, bb.z, bb.w};
#pragma unroll
            for (int i = 0; i < 8; ++i)
#pragma unroll
                for (int j = 0; j < 4; ++j) acc[i][j] += av[i] * bv[j];
        }
        __syncthreads();
    }

    float bias[4];
#pragma unroll
    for (int j = 0; j < 4; ++j) bias[j] = bo[tc * 4 + j];
#pragma unroll
    for (int i = 0; i < 8; ++i) {
        int b = tr * 8 + i;
        float* dst = out + OUT_OUTPUTS + ((size_t)b * S_ + t) * O_ + tc * 4;
        *(float4*)dst = make_float4(acc[i][0] + bias[0], acc[i][1] + bias[1],
                                    acc[i][2] + bias[2], acc[i][3] + bias[3]);
    }
}

extern "C" void kernel_launch(void* const* d_in, const int* in_sizes, int n_in,
                              void* d_out, int out_size) {
    const float* x     = (const float*)d_in[0];
    const float* Wp    = (const float*)d_in[1];
    const float* bp    = (const float*)d_in[2];
    const float* U     = (const float*)d_in[3];
    const float* V     = (const float*)d_in[4];
    const float* cbias = (const float*)d_in[5];
    const float* W_in  = (const float*)d_in[6];
    const float* W_Q   = (const float*)d_in[7];
    const float* W_K   = (const float*)d_in[8];
    const float* W_V   = (const float*)d_in[9];
    const float* Wo    = (const float*)d_in[10];
    const float* bo    = (const float*)d_in[11];
    float* out = (float*)d_out;

    static bool attr_done = false;
    if (!attr_done) {
        cudaFuncSetAttribute(prep_wcomb,      cudaFuncAttributeMaxDynamicSharedMemorySize, 132608);
        cudaFuncSetAttribute(gemm_in_kernel,  cudaFuncAttributeMaxDynamicSharedMemorySize, 131072);
        cudaFuncSetAttribute(rim_seq_kernel,  cudaFuncAttributeMaxDynamicSharedMemorySize, 215040);
        cudaFuncSetAttribute(gemm_out_kernel, cudaFuncAttributeMaxDynamicSharedMemorySize, 131072);
        attr_done = true;
    }

    prep_wcomb<<<M_, 256, 132608>>>(W_in, Wp);
    dim3 gA(16, S_);
    gemm_in_kernel<<<gA, 512, 131072>>>(x, W_in, bp, cbias, out);
    rim_seq_kernel<<<B_, 512, 215040>>>(U, V, W_Q, W_K, W_V, out);
    gemm_out_kernel<<<S_, 512, 131072>>>(Wo, bo, out);
}

// round 4
// speedup vs baseline: 1.3583x; 1.3583x over previous
#include <cuda_runtime.h>
#include <cuda_fp16.h>
#include <cuda_bf16.h>
#include <cstdint>
#include <cstddef>

#define B_  128
#define S_  512
#define I_  128
#define H_  128
#define M_  8
#define KD_ 16
#define R_  16
#define O_  128
#define MH_ 1024

#define OUT_OUTPUTS 0ull
#define OUT_HID     8388608ull
#define OUT_AIN     75497472ull
#define OUT_ACM     142606336ull
#define OUT_ATTN    209715200ull

// ---------------- scratch (no allocations allowed) ----------------
__device__ float g_P[(size_t)S_ * B_ * MH_];
__device__ float g_Wcomb[M_ * I_ * H_];
__device__ float g_biasP[MH_];
__device__ __align__(16) __nv_bfloat16 g_BinT_hi[M_ * 16384];
__device__ __align__(16) __nv_bfloat16 g_BinT_lo[M_ * 16384];
__device__ __align__(16) __nv_bfloat16 g_BpT_hi[M_ * 16384];
__device__ __align__(16) __nv_bfloat16 g_BpT_lo[M_ * 16384];
__device__ __align__(16) __nv_bfloat16 g_Wo_hi[O_ * MH_];
__device__ __align__(16) __nv_bfloat16 g_Wo_lo[O_ * MH_];

// ---------------- helpers ----------------
__device__ __forceinline__ uint32_t smem_u32(const void* p) {
    uint32_t a;
    asm("{ .reg .u64 t; cvta.to.shared.u64 t, %1; cvt.u32.u64 %0, t; }" : "=r"(a) : "l"(p));
    return a;
}

// SW128 blocked-atom layout for a 128x128 bf16 tile:
// atom = 8 rows x 64 bf16 (1024B); 16 atom-rows x 2 atom-cols.
__device__ __forceinline__ uint32_t swb(int n, int k) {
    uint32_t byte = ((uint32_t)((n >> 3) + (k >> 6) * 16)) * 1024u
                  + (uint32_t)(n & 7) * 128u + (uint32_t)(k & 63) * 2u;
    return byte ^ ((byte >> 3) & 0x70u);
}

__device__ __forceinline__ void split1(float v, uint16_t& h, uint16_t& l) {
    __nv_bfloat16 bh = __float2bfloat16(v);
    float r = v - __bfloat162float(bh);
    h = __bfloat16_as_ushort(bh);
    l = __bfloat16_as_ushort(__float2bfloat16(r));
}

__device__ __forceinline__ void ldsm4(uint32_t* r, uint32_t addr) {
    asm volatile("ldmatrix.sync.aligned.m8n8.x4.shared.b16 {%0,%1,%2,%3}, [%4];"
                 : "=r"(r[0]), "=r"(r[1]), "=r"(r[2]), "=r"(r[3]) : "r"(addr));
}

__device__ __forceinline__ void mma16816(float* c, const uint32_t* a, const uint32_t* b) {
    asm volatile("mma.sync.aligned.m16n8k16.row.col.f32.bf16.bf16.f32 "
                 "{%0,%1,%2,%3}, {%4,%5,%6,%7}, {%8,%9}, {%0,%1,%2,%3};"
                 : "+f"(c[0]), "+f"(c[1]), "+f"(c[2]), "+f"(c[3])
                 : "r"(a[0]), "r"(a[1]), "r"(a[2]), "r"(a[3]), "r"(b[0]), "r"(b[1]));
}

// smem layout for gemm kernels (4 x 32KB tiles)
#define A_HI 0
#define A_LO 32768
#define B_HI 65536
#define B_LO 98304
#define GEMM_SMEM 131072

// ---------------------------------------------------------------------------
// prep 0: Wcomb[m,i,o] = sum_h W_in[m,i,h] * Wp[m,o,h]
// ---------------------------------------------------------------------------
__global__ void __launch_bounds__(256) prep_wcomb(const float* __restrict__ W_in,
                                                  const float* __restrict__ Wp) {
    extern __shared__ float s0[];
    float* Wins = s0;
    float* Wps  = s0 + 16384;   // stride 129
    int m = blockIdx.x, tid = threadIdx.x;
    const float* wi = W_in + m * 16384;
    const float* wp = Wp   + m * 16384;
    for (int i = tid; i < 16384; i += 256) {
        Wins[i] = wi[i];
        Wps[(i >> 7) * 129 + (i & 127)] = wp[i];
    }
    __syncthreads();
    for (int idx = tid; idx < 16384; idx += 256) {
        int j = idx >> 7, o = idx & 127;
        const float* a = Wins + j * 128;
        const float* b = Wps + o * 129;
        float acc = 0.f;
#pragma unroll 16
        for (int i = 0; i < 128; ++i) acc += a[i] * b[i];
        g_Wcomb[m * 16384 + idx] = acc;
    }
}

// ---------------------------------------------------------------------------
// prep 1: transpose + bf16-split weights to [n][k], combine biases
// ---------------------------------------------------------------------------
__global__ void __launch_bounds__(256) prep_split(const float* __restrict__ W_in,
                                                  const float* __restrict__ Wo,
                                                  const float* __restrict__ bp,
                                                  const float* __restrict__ cbias) {
    int b = blockIdx.x, tid = threadIdx.x;
    if (b < 8) {
        int m = b;
        for (int idx = tid; idx < 16384; idx += 256) {
            int h = idx >> 7, i = idx & 127;
            uint16_t hi, lo;
            split1(W_in[m * 16384 + i * 128 + h], hi, lo);
            g_BinT_hi[m * 16384 + idx] = __ushort_as_bfloat16(hi);
            g_BinT_lo[m * 16384 + idx] = __ushort_as_bfloat16(lo);
        }
    } else if (b < 16) {
        int m = b - 8;
        for (int idx = tid; idx < 16384; idx += 256) {
            int o = idx >> 7, i = idx & 127;
            uint16_t hi, lo;
            split1(g_Wcomb[m * 16384 + i * 128 + o], hi, lo);
            g_BpT_hi[m * 16384 + idx] = __ushort_as_bfloat16(hi);
            g_BpT_lo[m * 16384 + idx] = __ushort_as_bfloat16(lo);
        }
    } else if (b < 32) {
        int s = b - 16;
        for (int idx = tid; idx < 8192; idx += 256) {
            int g = s * 8192 + idx;
            uint16_t hi, lo;
            split1(Wo[g], hi, lo);
            g_Wo_hi[g] = __ushort_as_bfloat16(hi);
            g_Wo_lo[g] = __ushort_as_bfloat16(lo);
        }
    } else {
        for (int idx = tid; idx < MH_; idx += 256) g_biasP[idx] = bp[idx] + cbias[idx];
    }
}

// ---------------------------------------------------------------------------
// GEMM A (mma.sync bf16-split): per t, A = x tile [128x128]; 16 B-blocks.
//  blk 0-7 : A_in -> d_out AIN;  blk 8-15: P + bias -> g_P
// ---------------------------------------------------------------------------
__global__ void __launch_bounds__(256)
gemm_in_mma(const float* __restrict__ x, float* __restrict__ out) {
    extern __shared__ char smc[];
    uint32_t sb = smem_u32(smc);
    int tid = threadIdx.x, w = tid >> 5, lane = tid & 31, t = blockIdx.x;

    {   // convert A tile (x rows, b-major) to split bf16, swizzled
        int rb = tid >> 1, half = tid & 1;
        const float4* xr = (const float4*)(x + ((size_t)rb * S_ + t) * I_ + half * 64);
#pragma unroll
        for (int q = 0; q < 16; ++q) {
            float4 v = xr[q];
            int k0 = half * 64 + q * 4;
            uint16_t h0, h1, h2, h3, l0, l1, l2, l3;
            split1(v.x, h0, l0); split1(v.y, h1, l1);
            split1(v.z, h2, l2); split1(v.w, h3, l3);
            uint2 hv = make_uint2((uint32_t)h0 | ((uint32_t)h1 << 16),
                                  (uint32_t)h2 | ((uint32_t)h3 << 16));
            uint2 lv = make_uint2((uint32_t)l0 | ((uint32_t)l1 << 16),
                                  (uint32_t)l2 | ((uint32_t)l3 << 16));
            uint32_t off = swb(rb, k0);
            *(uint2*)(smc + A_HI + off) = hv;
            *(uint2*)(smc + A_LO + off) = lv;
        }
    }

    // fragment address roles
    int lq = lane >> 3, ll = lane & 7;
    int a_row = w * 16 + ll + (lq & 1) * 8;
    int a_kadd = (lq >> 1) * 8;
    int b_rc = (lq >> 1) * 8 + ll;
    int b_kadd = (lq & 1) * 8;
    int c_row = w * 16 + (lane >> 2);
    int c_col = (lane & 3) * 2;

    for (int blk = 0; blk < 16; ++blk) {
        int m = blk & 7;
        bool isP = blk >= 8;
        const __nv_bfloat16* gh = (isP ? g_BpT_hi : g_BinT_hi) + m * 16384;
        const __nv_bfloat16* gl = (isP ? g_BpT_lo : g_BinT_lo) + m * 16384;
#pragma unroll
        for (int q = 0; q < 8; ++q) {
            int u = tid + q * 256;
            int n = u >> 4, k0 = (u & 15) * 8;
            uint4 vh = ((const uint4*)gh)[u];
            uint4 vl = ((const uint4*)gl)[u];
            uint32_t off = swb(n, k0);
            *(uint4*)(smc + B_HI + off) = vh;
            *(uint4*)(smc + B_LO + off) = vl;
        }
        __syncthreads();

        float c[16][4];
#pragma unroll
        for (int i = 0; i < 16; ++i)
#pragma unroll
            for (int j = 0; j < 4; ++j) c[i][j] = 0.f;

        for (int ks = 0; ks < 8; ++ks) {
            int k0 = ks * 16;
            uint32_t ah[4], al[4];
            uint32_t aoff = swb(a_row, k0 + a_kadd);
            ldsm4(ah, sb + A_HI + aoff);
            ldsm4(al, sb + A_LO + aoff);
#pragma unroll
            for (int np = 0; np < 8; ++np) {
                uint32_t bh[4], bl[4];
                uint32_t boff = swb(np * 16 + b_rc, k0 + b_kadd);
                ldsm4(bh, sb + B_HI + boff);
                ldsm4(bl, sb + B_LO + boff);
                mma16816(c[2 * np],     ah, bh);
                mma16816(c[2 * np],     ah, bl);
                mma16816(c[2 * np],     al, bh);
                mma16816(c[2 * np + 1], ah, bh + 2);
                mma16816(c[2 * np + 1], ah, bl + 2);
                mma16816(c[2 * np + 1], al, bh + 2);
            }
        }

        // writeback
        if (!isP) {
            float* d0 = out + OUT_AIN + ((size_t)t * B_ + c_row) * MH_ + m * H_;
            float* d1 = out + OUT_AIN + ((size_t)t * B_ + c_row + 8) * MH_ + m * H_;
#pragma unroll
            for (int nt = 0; nt < 16; ++nt) {
                int col = nt * 8 + c_col;
                *(float2*)(d0 + col) = make_float2(c[nt][0], c[nt][1]);
                *(float2*)(d1 + col) = make_float2(c[nt][2], c[nt][3]);
            }
        } else {
            float* d0 = g_P + ((size_t)t * B_ + c_row) * MH_ + m * H_;
            float* d1 = g_P + ((size_t)t * B_ + c_row + 8) * MH_ + m * H_;
#pragma unroll
            for (int nt = 0; nt < 16; ++nt) {
                int col = nt * 8 + c_col;
                float2 bi = *(const float2*)(g_biasP + m * H_ + col);
                *(float2*)(d0 + col) = make_float2(c[nt][0] + bi.x, c[nt][1] + bi.y);
                *(float2*)(d1 + col) = make_float2(c[nt][2] + bi.x, c[nt][3] + bi.y);
            }
        }
        __syncthreads();
    }
}

// ---------------------------------------------------------------------------
// GEMM C (mma.sync bf16-split): outputs[b,t,:] = hiddens[t,b,:].Wo^T + bo
// K=1024 in 8 chunks, C persistent in registers.
// ---------------------------------------------------------------------------
__global__ void __launch_bounds__(256)
gemm_out_mma(const float* __restrict__ bo, float* __restrict__ out) {
    extern __shared__ char smc[];
    uint32_t sb = smem_u32(smc);
    int tid = threadIdx.x, w = tid >> 5, lane = tid & 31, t = blockIdx.x;
    const float* hid = out + OUT_HID + (size_t)t * B_ * MH_;

    int lq = lane >> 3, ll = lane & 7;
    int a_row = w * 16 + ll + (lq & 1) * 8;
    int a_kadd = (lq >> 1) * 8;
    int b_rc = (lq >> 1) * 8 + ll;
    int b_kadd = (lq & 1) * 8;
    int c_row = w * 16 + (lane >> 2);
    int c_col = (lane & 3) * 2;

    float c[16][4];
#pragma unroll
    for (int i = 0; i < 16; ++i)
#pragma unroll
        for (int j = 0; j < 4; ++j) c[i][j] = 0.f;

    for (int kc = 0; kc < 8; ++kc) {
        {   // A chunk: hidden rows b, cols kc*128..+128, split to smem
            int rb = tid >> 1, half = tid & 1;
            const float4* ar = (const float4*)(hid + (size_t)rb * MH_ + kc * 128 + half * 64);
#pragma unroll
            for (int q = 0; q < 16; ++q) {
                float4 v = ar[q];
                int k0 = half * 64 + q * 4;
                uint16_t h0, h1, h2, h3, l0, l1, l2, l3;
                split1(v.x, h0, l0); split1(v.y, h1, l1);
                split1(v.z, h2, l2); split1(v.w, h3, l3);
                uint2 hv = make_uint2((uint32_t)h0 | ((uint32_t)h1 << 16),
                                      (uint32_t)h2 | ((uint32_t)h3 << 16));
                uint2 lv = make_uint2((uint32_t)l0 | ((uint32_t)l1 << 16),
                                      (uint32_t)l2 | ((uint32_t)l3 << 16));
                uint32_t off = swb(rb, k0);
                *(uint2*)(smc + A_HI + off) = hv;
                *(uint2*)(smc + A_LO + off) = lv;
            }
        }
#pragma unroll
        for (int q = 0; q < 8; ++q) {   // B chunk: Wo rows n, cols kc*128..+128
            int u = tid + q * 256;
            int n = u >> 4, k0 = (u & 15) * 8;
            uint4 vh = *(const uint4*)(g_Wo_hi + (size_t)n * MH_ + kc * 128 + k0);
            uint4 vl = *(const uint4*)(g_Wo_lo + (size_t)n * MH_ + kc * 128 + k0);
            uint32_t off = swb(n, k0);
            *(uint4*)(smc + B_HI + off) = vh;
            *(uint4*)(smc + B_LO + off) = vl;
        }
        __syncthreads();

        for (int ks = 0; ks < 8; ++ks) {
            int k0 = ks * 16;
            uint32_t ah[4], al[4];
            uint32_t aoff = swb(a_row, k0 + a_kadd);
            ldsm4(ah, sb + A_HI + aoff);
            ldsm4(al, sb + A_LO + aoff);
#pragma unroll
            for (int np = 0; np < 8; ++np) {
                uint32_t bh[4], bl[4];
                uint32_t boff = swb(np * 16 + b_rc, k0 + b_kadd);
                ldsm4(bh, sb + B_HI + boff);
                ldsm4(bl, sb + B_LO + boff);
                mma16816(c[2 * np],     ah, bh);
                mma16816(c[2 * np],     ah, bl);
                mma16816(c[2 * np],     al, bh);
                mma16816(c[2 * np + 1], ah, bh + 2);
                mma16816(c[2 * np + 1], ah, bl + 2);
                mma16816(c[2 * np + 1], al, bh + 2);
            }
        }
        __syncthreads();
    }

    float* d0 = out + OUT_OUTPUTS + ((size_t)c_row * S_ + t) * O_;
    float* d1 = out + OUT_OUTPUTS + ((size_t)(c_row + 8) * S_ + t) * O_;
#pragma unroll
    for (int nt = 0; nt < 16; ++nt) {
        int col = nt * 8 + c_col;
        float2 bi = *(const float2*)(bo + col);
        *(float2*)(d0 + col) = make_float2(c[nt][0] + bi.x, c[nt][1] + bi.y);
        *(float2*)(d1 + col) = make_float2(c[nt][2] + bi.x, c[nt][3] + bi.y);
    }
}

// ---------------------------------------------------------------------------
// Kernel B: sequential recurrence, one CTA per batch element. (unchanged)
// ---------------------------------------------------------------------------
__global__ void __launch_bounds__(512) rim_seq_kernel(const float* __restrict__ U,
                                                      const float* __restrict__ V,
                                                      const float* __restrict__ WQ,
                                                      const float* __restrict__ WK,
                                                      const float* __restrict__ WV,
                                                      float* __restrict__ out) {
    extern __shared__ float smf[];
    float* Us   = smf;
    float* Vs   = Us + 16384;
    float* wvd  = Vs + 16384;
    float* Ssm  = wvd + 1024;
    float* his  = Ssm + 1024;
    float* vcs  = his + 1024;
    float* tmp  = vcs + 1024;
    float* Kc   = tmp + 128;
    float* Qc   = Kc + 128;
    float* attn = Qc + 128;
    __half* WKh = (__half*)(attn + 64);
    __half* WQh = WKh + 16384;

    int tid = threadIdx.x, b = blockIdx.x;
    for (int i = tid; i < 16384; i += 512) {
        Us[i] = U[i];
        Vs[i] = V[i];
        WKh[i] = __float2half(WK[i]);
        WQh[i] = __float2half(WQ[i]);
    }
    for (int i = tid; i < 1024; i += 512) {
        int m = i >> 7, h = i & 127;
        wvd[i] = WV[m * 16384 + h * 128 + h];
        Ssm[i] = 0.f;
    }
    __syncthreads();

    int w = tid >> 5, lane = tid & 31;
    int ma = w >> 1, rbase = (w & 1) * 8, rl = lane >> 2, hq = lane & 3, rr = rbase + rl;
    int mc = w >> 1, isQ = w & 1, kk = lane >> 1, hh = lane & 1;
    const __half* Wch = (isQ ? WQh : WKh) + mc * 2048;
    float* Xc = isQ ? Qc : Kc;

    float p0 = g_P[(size_t)b * MH_ + tid];
    float p1 = g_P[(size_t)b * MH_ + tid + 512];

    for (int t = 0; t < S_; ++t) {
        {
            float acc = 0.f;
            const float* Su = Ssm + ma * 128;
            const float* Uu = Us + ma * 2048 + rr;
#pragma unroll 8
            for (int j = 0; j < 32; ++j) {
                int h = hq + 4 * j;
                acc += Su[h] * Uu[h * 16];
            }
            acc += __shfl_xor_sync(0xffffffffu, acc, 1);
            acc += __shfl_xor_sync(0xffffffffu, acc, 2);
            if (hq == 0) tmp[ma * 16 + rr] = acc;
        }
        __syncthreads();

        {
            float z0 = p0, z1 = p1;
            int i0 = tid, i1 = tid + 512;
            int m0 = i0 >> 7, h0 = i0 & 127;
            int m1 = i1 >> 7, h1 = i1 & 127;
            const float* t0 = tmp + m0 * 16;
            const float* t1 = tmp + m1 * 16;
            const float* V0 = Vs + m0 * 2048 + h0;
            const float* V1 = Vs + m1 * 2048 + h1;
#pragma unroll
            for (int r = 0; r < 16; ++r) {
                z0 += t0[r] * V0[r * 128];
                z1 += t1[r] * V1[r * 128];
            }
            float hin0 = tanhf(z0), hin1 = tanhf(z1);
            his[i0] = hin0; his[i1] = hin1;
            vcs[i0] = hin0 * wvd[i0];
            vcs[i1] = hin1 * wvd[i1];
        }
        if (t + 1 < S_) {
            size_t base = ((size_t)(t + 1) * B_ + b) * MH_;
            p0 = g_P[base + tid];
            p1 = g_P[base + tid + 512];
        }
        __syncthreads();

        {
            float acc = 0.f;
            const float* hm = his + mc * 128;
#pragma unroll 8
            for (int j = 0; j < 64; ++j) {
                int h = hh + 2 * j;
                acc += hm[h] * __half2float(Wch[h * 16 + kk]);
            }
            acc += __shfl_xor_sync(0xffffffffu, acc, 1);
            if (hh == 0) Xc[mc * 16 + kk] = acc;
        }
        __syncthreads();

        if (w < 8) {
            int n = lane & 7;
            const float* q = Qc + w * 16;
            const float* k2 = Kc + n * 16;
            float lg = 0.f;
#pragma unroll
            for (int k = 0; k < 16; ++k) lg += q[k] * k2[k];
            lg *= 0.25f;
            float mx = lg;
            mx = fmaxf(mx, __shfl_xor_sync(0xffffffffu, mx, 1));
            mx = fmaxf(mx, __shfl_xor_sync(0xffffffffu, mx, 2));
            mx = fmaxf(mx, __shfl_xor_sync(0xffffffffu, mx, 4));
            float e = expf(lg - mx);
            float sm2 = e;
            sm2 += __shfl_xor_sync(0xffffffffu, sm2, 1);
            sm2 += __shfl_xor_sync(0xffffffffu, sm2, 2);
            sm2 += __shfl_xor_sync(0xffffffffu, sm2, 4);
            float a3 = e / sm2;
            if (lane < 8) {
                attn[w * 8 + n] = a3;
                out[OUT_ATTN + ((size_t)t * B_ + b) * 64 + w * 8 + n] = a3;
            }
        }
        __syncthreads();

        {
            size_t gbase = ((size_t)t * B_ + b) * MH_;
#pragma unroll
            for (int rep = 0; rep < 2; ++rep) {
                int idx = tid + rep * 512;
                int n = idx >> 7, h = idx & 127;
                float ac = 0.f;
#pragma unroll
                for (int m = 0; m < 8; ++m) ac += attn[m * 8 + n] * vcs[m * 128 + h];
                float hnew = his[idx] + ac;
                out[OUT_ACM + gbase + idx] = ac;
                out[OUT_HID + gbase + idx] = hnew;
                Ssm[idx] = hnew;
            }
        }
        __syncthreads();
    }
}

extern "C" void kernel_launch(void* const* d_in, const int* in_sizes, int n_in,
                              void* d_out, int out_size) {
    const float* x     = (const float*)d_in[0];
    const float* Wp    = (const float*)d_in[1];
    const float* bp    = (const float*)d_in[2];
    const float* U     = (const float*)d_in[3];
    const float* V     = (const float*)d_in[4];
    const float* cbias = (const float*)d_in[5];
    const float* W_in  = (const float*)d_in[6];
    const float* W_Q   = (const float*)d_in[7];
    const float* W_K   = (const float*)d_in[8];
    const float* W_V   = (const float*)d_in[9];
    const float* Wo    = (const float*)d_in[10];
    const float* bo    = (const float*)d_in[11];
    float* out = (float*)d_out;

    static bool attr_done = false;
    if (!attr_done) {
        cudaFuncSetAttribute(prep_wcomb,     cudaFuncAttributeMaxDynamicSharedMemorySize, 132608);
        cudaFuncSetAttribute(gemm_in_mma,    cudaFuncAttributeMaxDynamicSharedMemorySize, GEMM_SMEM);
        cudaFuncSetAttribute(gemm_out_mma,   cudaFuncAttributeMaxDynamicSharedMemorySize, GEMM_SMEM);
        cudaFuncSetAttribute(rim_seq_kernel, cudaFuncAttributeMaxDynamicSharedMemorySize, 215040);
        attr_done = true;
    }

    prep_wcomb<<<M_, 256, 132608>>>(W_in, Wp);
    prep_split<<<33, 256>>>(W_in, Wo, bp, cbias);
    gemm_in_mma<<<S_, 256, GEMM_SMEM>>>(x, out);
    rim_seq_kernel<<<B_, 512, 215040>>>(U, V, W_Q, W_K, W_V, out);
    gemm_out_mma<<<S_, 256, GEMM_SMEM>>>(bo, out);
}